// round 9
// baseline (speedup 1.0000x reference)
#include <cuda_runtime.h>
#include <cuda_bf16.h>
#include <stdint.h>
#include <math.h>

#define B_ 64
#define W_ 256
#define N_ 128
#define L_ 64
#define WC 128
#define THREADS 512
#define PADK 72                    // bf16 row stride: 144B -> conflict-free ldmatrix

// smem byte offsets
#define OFF_AHI 0
#define OFF_ALO 18432
#define OFF_BHI 36864
#define OFF_BLO 55296
#define OFF_SXX 73728              // [128] f32 window norms
#define OFF_SSN (73728 + 512)      // [128] f32 shapelet norms
#define OFF_UMIN (73728 + 1024)    // [128] u32 min d^2 bits
#define OFF_RED (73728 + 1536)     // [4] f32
#define OFF_TKT (73728 + 1552)     // [1] int
#define SMEM_TOTAL (73728 + 1600)

__device__ float g_part[B_][2][N_];
__device__ int   g_cnt[B_];

__device__ __forceinline__ uint32_t smem_u32(const void* p) {
    uint32_t a;
    asm("{ .reg .u64 t; cvta.to.shared.u64 t, %1; cvt.u32.u64 %0, t; }" : "=r"(a) : "l"(p));
    return a;
}

#define LDSM_X4(r, addr) \
    asm volatile("ldmatrix.sync.aligned.m8n8.x4.shared.b16 {%0,%1,%2,%3}, [%4];" \
                 : "=r"((r)[0]), "=r"((r)[1]), "=r"((r)[2]), "=r"((r)[3]) : "r"(addr))

#define MMA_BF16(c, a, b0, b1) \
    asm volatile("mma.sync.aligned.m16n8k16.row.col.f32.bf16.bf16.f32 " \
                 "{%0,%1,%2,%3},{%4,%5,%6,%7},{%8,%9},{%0,%1,%2,%3};" \
                 : "+f"((c)[0]), "+f"((c)[1]), "+f"((c)[2]), "+f"((c)[3]) \
                 : "r"((a)[0]), "r"((a)[1]), "r"((a)[2]), "r"((a)[3]), "r"(b0), "r"(b1))

__global__ void __launch_bounds__(THREADS) fused_kernel(const float* __restrict__ x,
                                                        const float* __restrict__ sh,
                                                        const float* __restrict__ cw,
                                                        const float* __restrict__ cb,
                                                        float* __restrict__ out) {
    extern __shared__ char sm[];
    const uint32_t smb = smem_u32(sm);
    const int tid  = threadIdx.x;
    const int wid  = tid >> 5, lane = tid & 31;
    const int b    = blockIdx.x >> 1, half = blockIdx.x & 1;

    float* sxx = (float*)(sm + OFF_SXX);
    float* ssn = (float*)(sm + OFF_SSN);
    unsigned int* umin = (unsigned int*)(sm + OFF_UMIN);
    float* red = (float*)(sm + OFF_RED);
    int*   tkt = (int*)(sm + OFF_TKT);

    if (tid < N_) umin[tid] = 0x7F800000u;

    // ---- phase 1: 2 threads per row; 8x LDG.128 each; 1 shuffle for the norm ----
    {
        const int r256   = tid >> 1;            // 0..255: 0-127 = windows, 128-255 = shapelets
        const bool isA   = r256 < 128;
        const int row    = isA ? r256 : r256 - 128;
        const int cbase  = (tid & 1) * 32;      // column half of the row
        const float* src = (isA ? x + (size_t)(b * W_ + half * WC) * L_
                                : sh) + (size_t)row * L_ + cbase;
        char* thi = sm + (isA ? OFF_AHI : OFF_BHI);
        char* tlo = sm + (isA ? OFF_ALO : OFF_BLO);
        float nr = 0.f;
        #pragma unroll
        for (int i = 0; i < 8; i++) {
            float4 v = *(const float4*)(src + i * 4);
            nr = fmaf(v.x, v.x, nr); nr = fmaf(v.y, v.y, nr);
            nr = fmaf(v.z, v.z, nr); nr = fmaf(v.w, v.w, nr);
            __nv_bfloat162 h0, h1, l0, l1;
            h0.x = __float2bfloat16_rn(v.x); h0.y = __float2bfloat16_rn(v.y);
            h1.x = __float2bfloat16_rn(v.z); h1.y = __float2bfloat16_rn(v.w);
            l0.x = __float2bfloat16_rn(v.x - __bfloat162float(h0.x));
            l0.y = __float2bfloat16_rn(v.y - __bfloat162float(h0.y));
            l1.x = __float2bfloat16_rn(v.z - __bfloat162float(h1.x));
            l1.y = __float2bfloat16_rn(v.w - __bfloat162float(h1.y));
            uint32_t o = (uint32_t)(row * PADK + cbase + i * 4) * 2;
            *(__nv_bfloat162*)(thi + o)     = h0;
            *(__nv_bfloat162*)(thi + o + 4) = h1;
            *(__nv_bfloat162*)(tlo + o)     = l0;
            *(__nv_bfloat162*)(tlo + o + 4) = l1;
        }
        nr += __shfl_xor_sync(0xffffffffu, nr, 1);
        if ((tid & 1) == 0) (isA ? sxx : ssn)[row] = nr;
    }
    __syncthreads();

    // ---- phase 2: 16 warps, warp tile 32(M) x 32(N), K = 3 passes x 64 ----
    const int mbase = (wid & 3) * 32;
    const int nbase = (wid >> 2) * 32;

    float acc[2][4][4];
    #pragma unroll
    for (int mt = 0; mt < 2; mt++)
        #pragma unroll
        for (int j = 0; j < 4; j++)
            #pragma unroll
            for (int e = 0; e < 4; e++) acc[mt][j][e] = 0.f;

    const uint32_t a_off = (uint32_t)((mbase + (lane & 15)) * PADK + (lane >> 4) * 8) * 2;
    const uint32_t q = lane >> 3;
    const uint32_t b_off = (uint32_t)((nbase + ((q >> 1) << 3) + (lane & 7)) * PADK
                                      + (q & 1) * 8) * 2;

    const uint32_t aB[3] = {smb + OFF_AHI + a_off, smb + OFF_AHI + a_off, smb + OFF_ALO + a_off};
    const uint32_t bB[3] = {smb + OFF_BHI + b_off, smb + OFF_BLO + b_off, smb + OFF_BHI + b_off};

    #pragma unroll
    for (int p = 0; p < 3; p++) {
        #pragma unroll
        for (int ks = 0; ks < 4; ks++) {
            const uint32_t ko = ks * 32;       // 16 bf16 cols = 32 bytes
            uint32_t A0[4], A1[4], Bf[2][4];
            LDSM_X4(A0, aB[p] + ko);
            LDSM_X4(A1, aB[p] + 16 * PADK * 2 + ko);
            LDSM_X4(Bf[0], bB[p] + ko);
            LDSM_X4(Bf[1], bB[p] + 16 * PADK * 2 + ko);
            #pragma unroll
            for (int mt = 0; mt < 2; mt++)
                #pragma unroll
                for (int j = 0; j < 4; j++)
                    MMA_BF16(acc[mt][j], (mt ? A1 : A0),
                             Bf[j >> 1][(j & 1) * 2], Bf[j >> 1][(j & 1) * 2 + 1]);
        }
    }

    // ---- epilogue: d^2 = xr + sn - 2*dot; min over the warp's 32 rows ----
    {
        const int g = lane >> 2, t = lane & 3;
        const float xr0 = sxx[mbase + g],      xr1 = sxx[mbase + 8 + g];
        const float xr2 = sxx[mbase + 16 + g], xr3 = sxx[mbase + 24 + g];
        #pragma unroll
        for (int j = 0; j < 4; j++) {
            float v0 = fminf(fminf(fmaf(-2.f, acc[0][j][0], xr0), fmaf(-2.f, acc[0][j][2], xr1)),
                             fminf(fmaf(-2.f, acc[1][j][0], xr2), fmaf(-2.f, acc[1][j][2], xr3)));
            float v1 = fminf(fminf(fmaf(-2.f, acc[0][j][1], xr0), fmaf(-2.f, acc[0][j][3], xr1)),
                             fminf(fmaf(-2.f, acc[1][j][1], xr2), fmaf(-2.f, acc[1][j][3], xr3)));
            #pragma unroll
            for (int o = 4; o <= 16; o <<= 1) {
                v0 = fminf(v0, __shfl_xor_sync(0xffffffffu, v0, o));
                v1 = fminf(v1, __shfl_xor_sync(0xffffffffu, v1, o));
            }
            if (lane < 4) {
                int c0 = nbase + j * 8 + t * 2;
                atomicMin(&umin[c0],     __float_as_uint(fmaxf(v0 + ssn[c0], 0.f)));
                atomicMin(&umin[c0 + 1], __float_as_uint(fmaxf(v1 + ssn[c0 + 1], 0.f)));
            }
        }
    }
    __syncthreads();

    // ---- publish half-min, ticket; last block of the pair merges + classifies ----
    if (tid < N_) __stcg(&g_part[b][half][tid], __uint_as_float(umin[tid]));
    __threadfence();
    __syncthreads();
    if (tid == 0) tkt[0] = atomicAdd(&g_cnt[b], 1);
    __syncthreads();

    if (tkt[0] == 1) {
        __threadfence();
        float v = 0.f;
        if (tid < N_) {
            float other = __ldcg(&g_part[b][1 - half][tid]);
            float d2 = fminf(__uint_as_float(umin[tid]), other);
            v = sqrtf(fmaxf(d2, 0.f)) * cw[tid];
        }
        #pragma unroll
        for (int o = 16; o; o >>= 1) v += __shfl_xor_sync(0xffffffffu, v, o);
        if (tid < N_ && (tid & 31) == 0) red[tid >> 5] = v;
        __syncthreads();
        if (tid == 0) {
            float s = red[0] + red[1] + red[2] + red[3] + cb[0];
            out[b] = 1.f / (1.f + expf(-s));
            atomicExch(&g_cnt[b], 0);          // reset for next graph replay
        }
    }
}

extern "C" void kernel_launch(void* const* d_in, const int* in_sizes, int n_in,
                              void* d_out, int out_size) {
    const float* x  = (const float*)d_in[0];
    const float* sh = (const float*)d_in[1];
    const float* cw = (const float*)d_in[2];
    const float* cb = (const float*)d_in[3];
    float* out = (float*)d_out;

    cudaFuncSetAttribute(fused_kernel, cudaFuncAttributeMaxDynamicSharedMemorySize, SMEM_TOTAL);
    fused_kernel<<<2 * B_, THREADS, SMEM_TOTAL>>>(x, sh, cw, cb, out);
}

// round 10
// speedup vs baseline: 1.3452x; 1.3452x over previous
#include <cuda_runtime.h>
#include <cuda_bf16.h>
#include <stdint.h>
#include <math.h>

#define B_ 64
#define W_ 256
#define N_ 128
#define L_ 64
#define WC 128
#define THREADS 512
#define PADK 72                    // bf16 row stride: 144B -> conflict-free ldmatrix

// smem byte offsets
#define OFF_AHI 0
#define OFF_ALO 18432
#define OFF_BHI 36864
#define OFF_BLO 55296
#define OFF_SXX 73728              // [128] f32 window norms
#define OFF_SSN (73728 + 512)      // [128] f32 shapelet norms
#define OFF_UMIN (73728 + 1024)    // [128] u32 min d^2 bits
#define OFF_RED (73728 + 1536)     // [4] f32
#define OFF_TKT (73728 + 1552)     // [1] int
#define SMEM_TOTAL (73728 + 1600)

__device__ float g_part[B_][2][N_];
__device__ int   g_cnt[B_];

__device__ __forceinline__ uint32_t smem_u32(const void* p) {
    uint32_t a;
    asm("{ .reg .u64 t; cvta.to.shared.u64 t, %1; cvt.u32.u64 %0, t; }" : "=r"(a) : "l"(p));
    return a;
}

#define LDSM_X4(r, addr) \
    asm volatile("ldmatrix.sync.aligned.m8n8.x4.shared.b16 {%0,%1,%2,%3}, [%4];" \
                 : "=r"((r)[0]), "=r"((r)[1]), "=r"((r)[2]), "=r"((r)[3]) : "r"(addr))

#define MMA_BF16(c, a, b0, b1) \
    asm volatile("mma.sync.aligned.m16n8k16.row.col.f32.bf16.bf16.f32 " \
                 "{%0,%1,%2,%3},{%4,%5,%6,%7},{%8,%9},{%0,%1,%2,%3};" \
                 : "+f"((c)[0]), "+f"((c)[1]), "+f"((c)[2]), "+f"((c)[3]) \
                 : "r"((a)[0]), "r"((a)[1]), "r"((a)[2]), "r"((a)[3]), "r"(b0), "r"(b1))

__global__ void __launch_bounds__(THREADS) fused_kernel(const float* __restrict__ x,
                                                        const float* __restrict__ sh,
                                                        const float* __restrict__ cw,
                                                        const float* __restrict__ cb,
                                                        float* __restrict__ out) {
    extern __shared__ char sm[];
    const uint32_t smb = smem_u32(sm);
    const int tid  = threadIdx.x;
    const int wid  = tid >> 5, lane = tid & 31;
    const int b    = blockIdx.x >> 1, half = blockIdx.x & 1;

    float* sxx = (float*)(sm + OFF_SXX);
    float* ssn = (float*)(sm + OFF_SSN);
    unsigned int* umin = (unsigned int*)(sm + OFF_UMIN);
    float* red = (float*)(sm + OFF_RED);
    int*   tkt = (int*)(sm + OFF_TKT);

    if (tid < N_) umin[tid] = 0x7F800000u;

    // ---- phase 1: coalesced loads (2 rows / warp-instr), packed converts ----
    // Warps 0-7: x rows; warps 8-15: shapelet rows. 16 rows per warp.
    {
        const bool isA  = wid < 8;
        const int rbase = (wid & 7) * 16;
        const float* base = isA ? x + (size_t)(b * W_ + half * WC) * L_ : sh;
        char* thi = sm + (isA ? OFF_AHI : OFF_BHI);
        char* tlo = sm + (isA ? OFF_ALO : OFF_BLO);
        float* nrm = isA ? sxx : ssn;
        const int ro  = lane >> 4;           // 0/1: which of the 2 rows
        const int col = (lane & 15) * 4;     // 4 floats per lane

        #pragma unroll
        for (int it = 0; it < 8; it++) {
            const int r = rbase + it * 2 + ro;
            float4 v = *(const float4*)(base + (size_t)r * L_ + col);

            __nv_bfloat162 h0 = __float22bfloat162_rn(make_float2(v.x, v.y));
            __nv_bfloat162 h1 = __float22bfloat162_rn(make_float2(v.z, v.w));
            // exact hi-as-f32 via bit expansion (bf16 bits << 16)
            uint32_t u0 = *(uint32_t*)&h0, u1 = *(uint32_t*)&h1;
            float hx = __uint_as_float(u0 << 16), hy = __uint_as_float(u0 & 0xFFFF0000u);
            float hz = __uint_as_float(u1 << 16), hw = __uint_as_float(u1 & 0xFFFF0000u);
            __nv_bfloat162 l0 = __float22bfloat162_rn(make_float2(v.x - hx, v.y - hy));
            __nv_bfloat162 l1 = __float22bfloat162_rn(make_float2(v.z - hz, v.w - hw));

            const uint32_t o = (uint32_t)(r * PADK + col) * 2;
            *(uint2*)(thi + o) = make_uint2(u0, u1);
            uint32_t w0 = *(uint32_t*)&l0, w1 = *(uint32_t*)&l1;
            *(uint2*)(tlo + o) = make_uint2(w0, w1);

            float nr = fmaf(v.x, v.x, fmaf(v.y, v.y, fmaf(v.z, v.z, v.w * v.w)));
            nr += __shfl_xor_sync(0xffffffffu, nr, 1);
            nr += __shfl_xor_sync(0xffffffffu, nr, 2);
            nr += __shfl_xor_sync(0xffffffffu, nr, 4);
            nr += __shfl_xor_sync(0xffffffffu, nr, 8);
            if ((lane & 15) == 0) nrm[r] = nr;
        }
    }
    __syncthreads();

    // ---- phase 2: 16 warps, warp tile 32(M) x 32(N), K = 3 passes x 64 ----
    const int mbase = (wid & 3) * 32;
    const int nbase = (wid >> 2) * 32;

    float acc[2][4][4];
    #pragma unroll
    for (int mt = 0; mt < 2; mt++)
        #pragma unroll
        for (int j = 0; j < 4; j++)
            #pragma unroll
            for (int e = 0; e < 4; e++) acc[mt][j][e] = 0.f;

    const uint32_t a_off = (uint32_t)((mbase + (lane & 15)) * PADK + (lane >> 4) * 8) * 2;
    const uint32_t q = lane >> 3;
    const uint32_t b_off = (uint32_t)((nbase + ((q >> 1) << 3) + (lane & 7)) * PADK
                                      + (q & 1) * 8) * 2;

    const uint32_t aB[3] = {smb + OFF_AHI + a_off, smb + OFF_AHI + a_off, smb + OFF_ALO + a_off};
    const uint32_t bB[3] = {smb + OFF_BHI + b_off, smb + OFF_BLO + b_off, smb + OFF_BHI + b_off};

    #pragma unroll
    for (int p = 0; p < 3; p++) {
        #pragma unroll
        for (int ks = 0; ks < 4; ks++) {
            const uint32_t ko = ks * 32;       // 16 bf16 cols = 32 bytes
            uint32_t A0[4], A1[4], Bf[2][4];
            LDSM_X4(A0, aB[p] + ko);
            LDSM_X4(A1, aB[p] + 16 * PADK * 2 + ko);
            LDSM_X4(Bf[0], bB[p] + ko);
            LDSM_X4(Bf[1], bB[p] + 16 * PADK * 2 + ko);
            #pragma unroll
            for (int mt = 0; mt < 2; mt++)
                #pragma unroll
                for (int j = 0; j < 4; j++)
                    MMA_BF16(acc[mt][j], (mt ? A1 : A0),
                             Bf[j >> 1][(j & 1) * 2], Bf[j >> 1][(j & 1) * 2 + 1]);
        }
    }

    // ---- epilogue: d^2 = xr + sn - 2*dot; min over the warp's 32 rows ----
    {
        const int g = lane >> 2, t = lane & 3;
        const float xr0 = sxx[mbase + g],      xr1 = sxx[mbase + 8 + g];
        const float xr2 = sxx[mbase + 16 + g], xr3 = sxx[mbase + 24 + g];
        #pragma unroll
        for (int j = 0; j < 4; j++) {
            float v0 = fminf(fminf(fmaf(-2.f, acc[0][j][0], xr0), fmaf(-2.f, acc[0][j][2], xr1)),
                             fminf(fmaf(-2.f, acc[1][j][0], xr2), fmaf(-2.f, acc[1][j][2], xr3)));
            float v1 = fminf(fminf(fmaf(-2.f, acc[0][j][1], xr0), fmaf(-2.f, acc[0][j][3], xr1)),
                             fminf(fmaf(-2.f, acc[1][j][1], xr2), fmaf(-2.f, acc[1][j][3], xr3)));
            #pragma unroll
            for (int o = 4; o <= 16; o <<= 1) {
                v0 = fminf(v0, __shfl_xor_sync(0xffffffffu, v0, o));
                v1 = fminf(v1, __shfl_xor_sync(0xffffffffu, v1, o));
            }
            if (lane < 4) {
                int c0 = nbase + j * 8 + t * 2;
                atomicMin(&umin[c0],     __float_as_uint(fmaxf(v0 + ssn[c0], 0.f)));
                atomicMin(&umin[c0 + 1], __float_as_uint(fmaxf(v1 + ssn[c0 + 1], 0.f)));
            }
        }
    }
    __syncthreads();

    // ---- publish half-min, ticket; last block of the pair merges + classifies ----
    if (tid < N_) __stcg(&g_part[b][half][tid], __uint_as_float(umin[tid]));
    __threadfence();
    __syncthreads();
    if (tid == 0) tkt[0] = atomicAdd(&g_cnt[b], 1);
    __syncthreads();

    if (tkt[0] == 1) {
        __threadfence();
        float v = 0.f;
        if (tid < N_) {
            float other = __ldcg(&g_part[b][1 - half][tid]);
            float d2 = fminf(__uint_as_float(umin[tid]), other);
            v = sqrtf(fmaxf(d2, 0.f)) * cw[tid];
        }
        #pragma unroll
        for (int o = 16; o; o >>= 1) v += __shfl_xor_sync(0xffffffffu, v, o);
        if (tid < N_ && (tid & 31) == 0) red[tid >> 5] = v;
        __syncthreads();
        if (tid == 0) {
            float s = red[0] + red[1] + red[2] + red[3] + cb[0];
            out[b] = 1.f / (1.f + expf(-s));
            atomicExch(&g_cnt[b], 0);          // reset for next graph replay
        }
    }
}

extern "C" void kernel_launch(void* const* d_in, const int* in_sizes, int n_in,
                              void* d_out, int out_size) {
    const float* x  = (const float*)d_in[0];
    const float* sh = (const float*)d_in[1];
    const float* cw = (const float*)d_in[2];
    const float* cb = (const float*)d_in[3];
    float* out = (float*)d_out;

    cudaFuncSetAttribute(fused_kernel, cudaFuncAttributeMaxDynamicSharedMemorySize, SMEM_TOTAL);
    fused_kernel<<<2 * B_, THREADS, SMEM_TOTAL>>>(x, sh, cw, cb, out);
}